// round 3
// baseline (speedup 1.0000x reference)
#include <cuda_runtime.h>
#include <cstdint>
#include <math.h>

// Problem constants
#define Bn 2048
#define Hn 1024
#define En 6
#define OUTN 256

// GEMM tiling
#define BM 128
#define BNt 64
#define BKt 16
#define TM 8
#define TN 4

// ---------------- device scratch (no allocations allowed) ----------------
__device__ float  g_t[Bn * Hn];          // pre-BN activations / raw
__device__ float  g_h[Bn * Hn];          // post-BN activations
__device__ float  g_y[2 * Bn * Hn];      // expert outputs, slot 0 / slot 1
__device__ float  g_g1[Bn];
__device__ float  g_g2[Bn];
__device__ int    g_cnt[En];
__device__ int    g_list[En * Bn];       // token*2 + slot
__device__ float  g_loss[1];
__device__ double g_psum[8 * Hn];
__device__ double g_psq[8 * Hn];
__device__ float  g_scale[Hn];
__device__ float  g_shift[Hn];

// ---------------- threefry2x32 (bit-exact JAX) ----------------
__device__ __forceinline__ uint2 threefry2x32(uint32_t k0, uint32_t k1,
                                              uint32_t x0, uint32_t x1) {
    uint32_t k2 = k0 ^ k1 ^ 0x1BD11BDAu;
    x0 += k0; x1 += k1;
#define TF_RND(r) { x0 += x1; x1 = (x1 << (r)) | (x1 >> (32 - (r))); x1 ^= x0; }
    TF_RND(13) TF_RND(15) TF_RND(26) TF_RND(6)
    x0 += k1; x1 += k2 + 1u;
    TF_RND(17) TF_RND(29) TF_RND(16) TF_RND(24)
    x0 += k2; x1 += k0 + 2u;
    TF_RND(13) TF_RND(15) TF_RND(26) TF_RND(6)
    x0 += k0; x1 += k1 + 3u;
    TF_RND(17) TF_RND(29) TF_RND(16) TF_RND(24)
    x0 += k1; x1 += k2 + 4u;
    TF_RND(13) TF_RND(15) TF_RND(26) TF_RND(6)
    x0 += k2; x1 += k0 + 5u;
#undef TF_RND
    return make_uint2(x0, x1);
}

// ---------------- small utility kernels ----------------
__global__ void init_k() { g_loss[0] = 0.0f; }
__global__ void reset_cnt_k() { if (threadIdx.x < En) g_cnt[threadIdx.x] = 0; }

// ---------------- generic fp32 GEMM: C = A(MxK) @ B(KxN) + bias ----------------
__global__ __launch_bounds__(256) void gemm_bias(const float* __restrict__ A,
                                                 const float* __restrict__ B,
                                                 const float* __restrict__ bias,
                                                 float* __restrict__ C,
                                                 int K, int N) {
    __shared__ float As[BKt][BM];
    __shared__ float Bs[BKt][BNt];
    const int tid = threadIdx.x;
    const int m0 = blockIdx.y * BM;
    const int n0 = blockIdx.x * BNt;
    const int tx = tid & 15;      // 16 col groups of TN=4
    const int ty = tid >> 4;      // 16 row groups of TM=8

    float acc[TM][TN];
#pragma unroll
    for (int i = 0; i < TM; i++)
#pragma unroll
        for (int j = 0; j < TN; j++) acc[i][j] = 0.0f;

    for (int k0 = 0; k0 < K; k0 += BKt) {
#pragma unroll
        for (int it = 0; it < 2; it++) {
            int id = tid + it * 256;           // 512 float4 loads for 128x16 A tile
            int m = id >> 2;
            int kq = (id & 3) << 2;
            float4 v = *reinterpret_cast<const float4*>(A + (size_t)(m0 + m) * K + k0 + kq);
            As[kq + 0][m] = v.x; As[kq + 1][m] = v.y;
            As[kq + 2][m] = v.z; As[kq + 3][m] = v.w;
        }
        {
            int kk = tid >> 4;                 // 16 rows
            int n4 = (tid & 15) << 2;          // 64 cols
            float4 v = *reinterpret_cast<const float4*>(B + (size_t)(k0 + kk) * N + n0 + n4);
            *reinterpret_cast<float4*>(&Bs[kk][n4]) = v;
        }
        __syncthreads();
#pragma unroll
        for (int k = 0; k < BKt; k++) {
            float4 a0 = *reinterpret_cast<const float4*>(&As[k][ty * TM]);
            float4 a1 = *reinterpret_cast<const float4*>(&As[k][ty * TM + 4]);
            float4 bv = *reinterpret_cast<const float4*>(&Bs[k][tx * TN]);
            float aa[TM] = {a0.x, a0.y, a0.z, a0.w, a1.x, a1.y, a1.z, a1.w};
            float bb[TN] = {bv.x, bv.y, bv.z, bv.w};
#pragma unroll
            for (int i = 0; i < TM; i++)
#pragma unroll
                for (int j = 0; j < TN; j++)
                    acc[i][j] = fmaf(aa[i], bb[j], acc[i][j]);
        }
        __syncthreads();
    }
#pragma unroll
    for (int i = 0; i < TM; i++) {
        int m = m0 + ty * TM + i;
        float4 o;
        o.x = acc[i][0] + bias[n0 + tx * TN + 0];
        o.y = acc[i][1] + bias[n0 + tx * TN + 1];
        o.z = acc[i][2] + bias[n0 + tx * TN + 2];
        o.w = acc[i][3] + bias[n0 + tx * TN + 3];
        *reinterpret_cast<float4*>(C + (size_t)m * N + n0 + tx * TN) = o;
    }
}

// ---------------- gating: softmax/top2/threefry + list build ----------------
__global__ void gating_k(const float* __restrict__ WG, int layer) {
    int gw = (blockIdx.x * blockDim.x + threadIdx.x) >> 5;
    int lane = threadIdx.x & 31;
    if (gw >= Bn) return;
    const float* xr = g_t + (size_t)gw * Hn;
    float acc[En];
#pragma unroll
    for (int e = 0; e < En; e++) acc[e] = 0.0f;
    for (int k = lane; k < Hn; k += 32) {
        float xv = xr[k];
#pragma unroll
        for (int e = 0; e < En; e++) acc[e] = fmaf(xv, WG[k * En + e], acc[e]);
    }
#pragma unroll
    for (int e = 0; e < En; e++)
#pragma unroll
        for (int off = 16; off > 0; off >>= 1)
            acc[e] += __shfl_xor_sync(0xffffffffu, acc[e], off);

    if (lane != 0) return;
    // softmax (match jax.nn.softmax: subtract max, exp, normalize)
    float mx = acc[0];
#pragma unroll
    for (int e = 1; e < En; e++) mx = fmaxf(mx, acc[e]);
    float p[En]; float s = 0.0f;
#pragma unroll
    for (int e = 0; e < En; e++) { p[e] = expf(acc[e] - mx); s += p[e]; }
#pragma unroll
    for (int e = 0; e < En; e++) p[e] = p[e] / s;
    // argmax (first-max semantics like jnp.argmax)
    int i1 = 0; float v1 = p[0];
#pragma unroll
    for (int e = 1; e < En; e++) if (p[e] > v1) { v1 = p[e]; i1 = e; }
    int i2 = (i1 == 0) ? 1 : 0; float v2 = p[i2];
#pragma unroll
    for (int e = 0; e < En; e++)
        if (e != i1 && p[e] > v2) { v2 = p[e]; i2 = e; }

    atomicAdd(&g_loss[0], v1);  // raw top-1 prob (load balance loss term)

    float den = v1 + v2 + 1e-9f;
    float g1n = v1 / den, g2n = v2 / den;

    // JAX: key_i = fold_in(key(42), layer); u = uniform(key_i, (2048,1))
    // fold_in is config-independent: threefry_2x32(key, [0, layer])
    uint2 ki = threefry2x32(0u, 42u, 0u, (uint32_t)layer);
    int b = gw;
    // PARTITIONABLE threefry (jax_threefry_partitionable=True, modern default):
    // element b uses its own 64-bit counter: hi = b>>32 = 0, lo = b.
    // For 32-bit draws the two threefry output words are XOR-folded.
    uint2 r = threefry2x32(ki.x, ki.y, 0u, (uint32_t)b);
    uint32_t bits = r.x ^ r.y;
    float u = __uint_as_float((bits >> 9) | 0x3f800000u) - 1.0f;
    bool keep2 = u < (g2n / 0.2f);

    g_g1[b] = g1n;
    g_g2[b] = keep2 ? g2n : 0.0f;
    int pos = atomicAdd(&g_cnt[i1], 1);
    g_list[i1 * Bn + pos] = b * 2;
    if (keep2) {
        int pos2 = atomicAdd(&g_cnt[i2], 1);
        g_list[i2 * Bn + pos2] = b * 2 + 1;
    }
}

// ---------------- expert GEMM: gather rows from g_t, relu, scatter to g_y ----------------
__global__ __launch_bounds__(256) void expert_gemm(const float* __restrict__ W1full, int layer) {
    const int e = blockIdx.z;
    const int count = g_cnt[e];
    const int m0 = blockIdx.y * BM;
    if (m0 >= count) return;
    const float* __restrict__ W1 = W1full + ((size_t)layer * En + e) * Hn * Hn;

    __shared__ float As[BKt][BM];
    __shared__ float Bs[BKt][BNt];
    __shared__ int toks[BM];
    __shared__ int slots[BM];
    const int tid = threadIdx.x;
    const int n0 = blockIdx.x * BNt;
    const int tx = tid & 15;
    const int ty = tid >> 4;

    if (tid < BM) {
        int rr = m0 + tid;
        int v = (rr < count) ? g_list[e * Bn + rr] : -1;
        toks[tid] = (v < 0) ? -1 : (v >> 1);
        slots[tid] = (v < 0) ? 0 : (v & 1);
    }
    __syncthreads();

    float acc[TM][TN];
#pragma unroll
    for (int i = 0; i < TM; i++)
#pragma unroll
        for (int j = 0; j < TN; j++) acc[i][j] = 0.0f;

    for (int k0 = 0; k0 < Hn; k0 += BKt) {
#pragma unroll
        for (int it = 0; it < 2; it++) {
            int id = tid + it * 256;
            int m = id >> 2;
            int kq = (id & 3) << 2;
            int tok = toks[m];
            float4 v = make_float4(0.f, 0.f, 0.f, 0.f);
            if (tok >= 0)
                v = *reinterpret_cast<const float4*>(g_t + (size_t)tok * Hn + k0 + kq);
            As[kq + 0][m] = v.x; As[kq + 1][m] = v.y;
            As[kq + 2][m] = v.z; As[kq + 3][m] = v.w;
        }
        {
            int kk = tid >> 4;
            int n4 = (tid & 15) << 2;
            float4 v = *reinterpret_cast<const float4*>(W1 + (size_t)(k0 + kk) * Hn + n0 + n4);
            *reinterpret_cast<float4*>(&Bs[kk][n4]) = v;
        }
        __syncthreads();
#pragma unroll
        for (int k = 0; k < BKt; k++) {
            float4 a0 = *reinterpret_cast<const float4*>(&As[k][ty * TM]);
            float4 a1 = *reinterpret_cast<const float4*>(&As[k][ty * TM + 4]);
            float4 bv = *reinterpret_cast<const float4*>(&Bs[k][tx * TN]);
            float aa[TM] = {a0.x, a0.y, a0.z, a0.w, a1.x, a1.y, a1.z, a1.w};
            float bb[TN] = {bv.x, bv.y, bv.z, bv.w};
#pragma unroll
            for (int i = 0; i < TM; i++)
#pragma unroll
                for (int j = 0; j < TN; j++)
                    acc[i][j] = fmaf(aa[i], bb[j], acc[i][j]);
        }
        __syncthreads();
    }
#pragma unroll
    for (int i = 0; i < TM; i++) {
        int midx = ty * TM + i;
        int tok = toks[midx];
        if (tok < 0) continue;
        float4 o;
        o.x = fmaxf(acc[i][0], 0.f);
        o.y = fmaxf(acc[i][1], 0.f);
        o.z = fmaxf(acc[i][2], 0.f);
        o.w = fmaxf(acc[i][3], 0.f);
        *reinterpret_cast<float4*>(g_y + (size_t)slots[midx] * (Bn * Hn)
                                   + (size_t)tok * Hn + n0 + tx * TN) = o;
    }
}

// ---------------- combine: t += g1*y0 + g2*y1 ----------------
__global__ void combine_k() {
    size_t i = (size_t)blockIdx.x * 256 + threadIdx.x;  // float4 index over Bn*Hn/4
    int b = (int)(i >> 8);                              // Hn/4 = 256 float4 per row
    float G1 = g_g1[b], G2 = g_g2[b];
    float4 t  = reinterpret_cast<float4*>(g_t)[i];
    float4 y0 = reinterpret_cast<const float4*>(g_y)[i];
    float4 y1 = reinterpret_cast<const float4*>(g_y)[(size_t)(Bn * Hn / 4) + i];
    t.x += G1 * y0.x + G2 * y1.x;
    t.y += G1 * y0.y + G2 * y1.y;
    t.z += G1 * y0.z + G2 * y1.z;
    t.w += G1 * y0.w + G2 * y1.w;
    reinterpret_cast<float4*>(g_t)[i] = t;
}

// ---------------- batchnorm stats (double partial sums, deterministic) ----------------
__global__ void bn_partial_k() {
    __shared__ double ss[8][33];
    int tx = threadIdx.x & 31, ty = threadIdx.x >> 5;
    int col = blockIdx.x * 32 + tx;
    int r0 = blockIdx.y * 256;
    double s = 0.0, q = 0.0;
#pragma unroll 4
    for (int j = 0; j < 32; j++) {
        float v = g_t[(size_t)(r0 + ty + j * 8) * Hn + col];
        s += (double)v;
        q += (double)v * (double)v;
    }
    ss[ty][tx] = s; __syncthreads();
    if (ty == 0) {
        for (int j = 1; j < 8; j++) s += ss[j][tx];
        g_psum[blockIdx.y * Hn + col] = s;
    }
    __syncthreads();
    ss[ty][tx] = q; __syncthreads();
    if (ty == 0) {
        for (int j = 1; j < 8; j++) q += ss[j][tx];
        g_psq[blockIdx.y * Hn + col] = q;
    }
}

__global__ void bn_final_k(const float* __restrict__ gamma, const float* __restrict__ beta) {
    int col = blockIdx.x * 256 + threadIdx.x;
    double s = 0.0, q = 0.0;
    for (int j = 0; j < 8; j++) { s += g_psum[j * Hn + col]; q += g_psq[j * Hn + col]; }
    double mu = s / (double)Bn;
    float var = (float)(q / (double)Bn - mu * mu);
    float r = rsqrtf(var + 1e-5f);
    float a = gamma[col] * r;
    g_scale[col] = a;
    g_shift[col] = beta[col] - (float)mu * a;
}

__global__ void bn_apply_k() {
    size_t i = (size_t)blockIdx.x * 256 + threadIdx.x;  // float4 index
    int col = (int)((i & (Hn / 4 - 1)) << 2);
    float4 v = reinterpret_cast<const float4*>(g_t)[i];
    v.x = fmaxf(fmaf(v.x, g_scale[col + 0], g_shift[col + 0]), 0.f);
    v.y = fmaxf(fmaf(v.y, g_scale[col + 1], g_shift[col + 1]), 0.f);
    v.z = fmaxf(fmaf(v.z, g_scale[col + 2], g_shift[col + 2]), 0.f);
    v.w = fmaxf(fmaf(v.w, g_scale[col + 3], g_shift[col + 3]), 0.f);
    reinterpret_cast<float4*>(g_h)[i] = v;
}

// ---------------- loss write ----------------
__global__ void loss_k(float* __restrict__ out, int out_size) {
    if (out_size > Bn * OUTN)
        out[Bn * OUTN] = 0.01f * ((float)En / (float)Bn) * g_loss[0];
}

// ---------------- launcher ----------------
extern "C" void kernel_launch(void* const* d_in, const int* in_sizes, int n_in,
                              void* d_out, int out_size) {
    const float* x      = (const float*)d_in[0];
    const float* in_W   = (const float*)d_in[1];
    const float* in_b   = (const float*)d_in[2];
    const float* in_g   = (const float*)d_in[3];
    const float* in_be  = (const float*)d_in[4];
    const float* sp_W   = (const float*)d_in[5];
    const float* sp_b   = (const float*)d_in[6];
    const float* sp_g   = (const float*)d_in[7];
    const float* sp_be  = (const float*)d_in[8];
    const float* sp_gate= (const float*)d_in[9];
    const float* sp_w1  = (const float*)d_in[10];
    const float* dn_W   = (const float*)d_in[11];
    const float* dn_b   = (const float*)d_in[12];
    const float* dn_g   = (const float*)d_in[13];
    const float* dn_be  = (const float*)d_in[14];
    const float* out_W  = (const float*)d_in[15];
    const float* out_b  = (const float*)d_in[16];
    float* out = (float*)d_out;

    float* pt = nullptr; float* ph = nullptr;
    cudaGetSymbolAddress((void**)&pt, g_t);
    cudaGetSymbolAddress((void**)&ph, g_h);

    dim3 gemmGrid(Hn / BNt, Bn / BM);
    dim3 bnPartGrid(Hn / 32, 8);
    const int ew = Bn * Hn / 4 / 256;   // 2048 blocks for elementwise kernels

    init_k<<<1, 1>>>();

    // input layer: relu(bn(x @ in_W + in_b))
    gemm_bias<<<gemmGrid, 256>>>(x, in_W, in_b, pt, 2048, Hn);
    bn_partial_k<<<bnPartGrid, 256>>>();
    bn_final_k<<<Hn / 256, 256>>>(in_g, in_be);
    bn_apply_k<<<ew, 256>>>();

    // 4 sparse (MoE) layers
    for (int i = 0; i < 4; i++) {
        gemm_bias<<<gemmGrid, 256>>>(ph, sp_W + (size_t)i * Hn * Hn,
                                     sp_b + (size_t)i * Hn, pt, Hn, Hn);
        reset_cnt_k<<<1, 32>>>();
        gating_k<<<Bn / 8, 256>>>(sp_gate + (size_t)i * Hn * En, i);
        dim3 eg(Hn / BNt, Bn / BM, En);
        expert_gemm<<<eg, 256>>>(sp_w1, i);
        combine_k<<<ew, 256>>>();
        bn_partial_k<<<bnPartGrid, 256>>>();
        bn_final_k<<<Hn / 256, 256>>>(sp_g + (size_t)i * Hn, sp_be + (size_t)i * Hn);
        bn_apply_k<<<ew, 256>>>();
    }

    // 4 dense layers
    for (int i = 0; i < 4; i++) {
        gemm_bias<<<gemmGrid, 256>>>(ph, dn_W + (size_t)i * Hn * Hn,
                                     dn_b + (size_t)i * Hn, pt, Hn, Hn);
        bn_partial_k<<<bnPartGrid, 256>>>();
        bn_final_k<<<Hn / 256, 256>>>(dn_g + (size_t)i * Hn, dn_be + (size_t)i * Hn);
        bn_apply_k<<<ew, 256>>>();
    }

    // output projection + loss
    dim3 outGrid(OUTN / BNt, Bn / BM);
    gemm_bias<<<outGrid, 256>>>(ph, out_W, out_b, out, Hn, OUTN);
    loss_k<<<1, 1>>>(out, out_size);
}

// round 4
// speedup vs baseline: 1.0031x; 1.0031x over previous
#include <cuda_runtime.h>
#include <cstdint>
#include <math.h>

// Problem constants
#define Bn 2048
#define Hn 1024
#define En 6
#define OUTN 256

// GEMM tiling
#define BM 128
#define BNt 64
#define BKt 16
#define TM 8
#define TN 4

// ---------------- device scratch (no allocations allowed) ----------------
__device__ float  g_t[Bn * Hn];          // pre-BN activations / raw
__device__ float  g_h[Bn * Hn];          // post-BN activations
__device__ float  g_y[2 * Bn * Hn];      // expert outputs, slot 0 / slot 1
__device__ float  g_g1[Bn];
__device__ float  g_g2[Bn];
__device__ int    g_cnt[En];
__device__ int    g_list[En * Bn];       // token*2 + slot
__device__ float  g_loss[1];
__device__ double g_psum[8 * Hn];
__device__ double g_psq[8 * Hn];
__device__ float  g_scale[Hn];
__device__ float  g_shift[Hn];

// ---------------- threefry2x32 (bit-exact JAX) ----------------
__device__ __forceinline__ uint2 threefry2x32(uint32_t k0, uint32_t k1,
                                              uint32_t x0, uint32_t x1) {
    uint32_t k2 = k0 ^ k1 ^ 0x1BD11BDAu;
    x0 += k0; x1 += k1;
#define TF_RND(r) { x0 += x1; x1 = (x1 << (r)) | (x1 >> (32 - (r))); x1 ^= x0; }
    TF_RND(13) TF_RND(15) TF_RND(26) TF_RND(6)
    x0 += k1; x1 += k2 + 1u;
    TF_RND(17) TF_RND(29) TF_RND(16) TF_RND(24)
    x0 += k2; x1 += k0 + 2u;
    TF_RND(13) TF_RND(15) TF_RND(26) TF_RND(6)
    x0 += k0; x1 += k1 + 3u;
    TF_RND(17) TF_RND(29) TF_RND(16) TF_RND(24)
    x0 += k1; x1 += k2 + 4u;
    TF_RND(13) TF_RND(15) TF_RND(26) TF_RND(6)
    x0 += k2; x1 += k0 + 5u;
#undef TF_RND
    return make_uint2(x0, x1);
}

// ---------------- small utility kernels ----------------
__global__ void init_k() { g_loss[0] = 0.0f; }
__global__ void reset_cnt_k() { if (threadIdx.x < En) g_cnt[threadIdx.x] = 0; }

// ---------------- generic fp32 GEMM: C = A(MxK) @ B(KxN) + bias ----------------
__global__ __launch_bounds__(256) void gemm_bias(const float* __restrict__ A,
                                                 const float* __restrict__ B,
                                                 const float* __restrict__ bias,
                                                 float* __restrict__ C,
                                                 int K, int N) {
    __shared__ float As[BKt][BM];
    __shared__ float Bs[BKt][BNt];
    const int tid = threadIdx.x;
    const int m0 = blockIdx.y * BM;
    const int n0 = blockIdx.x * BNt;
    const int tx = tid & 15;      // 16 col groups of TN=4
    const int ty = tid >> 4;      // 16 row groups of TM=8

    float acc[TM][TN];
#pragma unroll
    for (int i = 0; i < TM; i++)
#pragma unroll
        for (int j = 0; j < TN; j++) acc[i][j] = 0.0f;

    for (int k0 = 0; k0 < K; k0 += BKt) {
#pragma unroll
        for (int it = 0; it < 2; it++) {
            int id = tid + it * 256;           // 512 float4 loads for 128x16 A tile
            int m = id >> 2;
            int kq = (id & 3) << 2;
            float4 v = *reinterpret_cast<const float4*>(A + (size_t)(m0 + m) * K + k0 + kq);
            As[kq + 0][m] = v.x; As[kq + 1][m] = v.y;
            As[kq + 2][m] = v.z; As[kq + 3][m] = v.w;
        }
        {
            int kk = tid >> 4;                 // 16 rows
            int n4 = (tid & 15) << 2;          // 64 cols
            float4 v = *reinterpret_cast<const float4*>(B + (size_t)(k0 + kk) * N + n0 + n4);
            *reinterpret_cast<float4*>(&Bs[kk][n4]) = v;
        }
        __syncthreads();
#pragma unroll
        for (int k = 0; k < BKt; k++) {
            float4 a0 = *reinterpret_cast<const float4*>(&As[k][ty * TM]);
            float4 a1 = *reinterpret_cast<const float4*>(&As[k][ty * TM + 4]);
            float4 bv = *reinterpret_cast<const float4*>(&Bs[k][tx * TN]);
            float aa[TM] = {a0.x, a0.y, a0.z, a0.w, a1.x, a1.y, a1.z, a1.w};
            float bb[TN] = {bv.x, bv.y, bv.z, bv.w};
#pragma unroll
            for (int i = 0; i < TM; i++)
#pragma unroll
                for (int j = 0; j < TN; j++)
                    acc[i][j] = fmaf(aa[i], bb[j], acc[i][j]);
        }
        __syncthreads();
    }
#pragma unroll
    for (int i = 0; i < TM; i++) {
        int m = m0 + ty * TM + i;
        float4 o;
        o.x = acc[i][0] + bias[n0 + tx * TN + 0];
        o.y = acc[i][1] + bias[n0 + tx * TN + 1];
        o.z = acc[i][2] + bias[n0 + tx * TN + 2];
        o.w = acc[i][3] + bias[n0 + tx * TN + 3];
        *reinterpret_cast<float4*>(C + (size_t)m * N + n0 + tx * TN) = o;
    }
}

// ---------------- gating: softmax/top2/threefry + list build ----------------
__global__ void gating_k(const float* __restrict__ WG, int layer) {
    int gw = (blockIdx.x * blockDim.x + threadIdx.x) >> 5;
    int lane = threadIdx.x & 31;
    if (gw >= Bn) return;
    const float* xr = g_t + (size_t)gw * Hn;
    float acc[En];
#pragma unroll
    for (int e = 0; e < En; e++) acc[e] = 0.0f;
    for (int k = lane; k < Hn; k += 32) {
        float xv = xr[k];
#pragma unroll
        for (int e = 0; e < En; e++) acc[e] = fmaf(xv, WG[k * En + e], acc[e]);
    }
#pragma unroll
    for (int e = 0; e < En; e++)
#pragma unroll
        for (int off = 16; off > 0; off >>= 1)
            acc[e] += __shfl_xor_sync(0xffffffffu, acc[e], off);

    if (lane != 0) return;
    // softmax (match jax.nn.softmax: subtract max, exp, normalize)
    float mx = acc[0];
#pragma unroll
    for (int e = 1; e < En; e++) mx = fmaxf(mx, acc[e]);
    float p[En]; float s = 0.0f;
#pragma unroll
    for (int e = 0; e < En; e++) { p[e] = expf(acc[e] - mx); s += p[e]; }
#pragma unroll
    for (int e = 0; e < En; e++) p[e] = p[e] / s;
    // argmax (first-max semantics like jnp.argmax)
    int i1 = 0; float v1 = p[0];
#pragma unroll
    for (int e = 1; e < En; e++) if (p[e] > v1) { v1 = p[e]; i1 = e; }
    int i2 = (i1 == 0) ? 1 : 0; float v2 = p[i2];
#pragma unroll
    for (int e = 0; e < En; e++)
        if (e != i1 && p[e] > v2) { v2 = p[e]; i2 = e; }

    atomicAdd(&g_loss[0], v1);  // raw top-1 prob (load balance loss term)

    float den = v1 + v2 + 1e-9f;
    float g1n = v1 / den, g2n = v2 / den;

    // JAX: key_i = fold_in(key(42), layer); u = uniform(key_i, (2048,1))
    // fold_in is config-independent: threefry_2x32(key, [0, layer])
    uint2 ki = threefry2x32(0u, 42u, 0u, (uint32_t)layer);
    int b = gw;
    // PARTITIONABLE threefry (jax_threefry_partitionable=True, modern default):
    // element b uses its own 64-bit counter: hi = b>>32 = 0, lo = b.
    // For 32-bit draws the two threefry output words are XOR-folded.
    uint2 r = threefry2x32(ki.x, ki.y, 0u, (uint32_t)b);
    uint32_t bits = r.x ^ r.y;
    float u = __uint_as_float((bits >> 9) | 0x3f800000u) - 1.0f;
    bool keep2 = u < (g2n / 0.2f);

    g_g1[b] = g1n;
    g_g2[b] = keep2 ? g2n : 0.0f;
    int pos = atomicAdd(&g_cnt[i1], 1);
    g_list[i1 * Bn + pos] = b * 2;
    if (keep2) {
        int pos2 = atomicAdd(&g_cnt[i2], 1);
        g_list[i2 * Bn + pos2] = b * 2 + 1;
    }
}

// ---------------- expert GEMM: gather rows from g_t, relu, scatter to g_y ----------------
__global__ __launch_bounds__(256) void expert_gemm(const float* __restrict__ W1full, int layer) {
    const int e = blockIdx.z;
    const int count = g_cnt[e];
    const int m0 = blockIdx.y * BM;
    if (m0 >= count) return;
    const float* __restrict__ W1 = W1full + ((size_t)layer * En + e) * Hn * Hn;

    __shared__ float As[BKt][BM];
    __shared__ float Bs[BKt][BNt];
    __shared__ int toks[BM];
    __shared__ int slots[BM];
    const int tid = threadIdx.x;
    const int n0 = blockIdx.x * BNt;
    const int tx = tid & 15;
    const int ty = tid >> 4;

    if (tid < BM) {
        int rr = m0 + tid;
        int v = (rr < count) ? g_list[e * Bn + rr] : -1;
        toks[tid] = (v < 0) ? -1 : (v >> 1);
        slots[tid] = (v < 0) ? 0 : (v & 1);
    }
    __syncthreads();

    float acc[TM][TN];
#pragma unroll
    for (int i = 0; i < TM; i++)
#pragma unroll
        for (int j = 0; j < TN; j++) acc[i][j] = 0.0f;

    for (int k0 = 0; k0 < Hn; k0 += BKt) {
#pragma unroll
        for (int it = 0; it < 2; it++) {
            int id = tid + it * 256;
            int m = id >> 2;
            int kq = (id & 3) << 2;
            int tok = toks[m];
            float4 v = make_float4(0.f, 0.f, 0.f, 0.f);
            if (tok >= 0)
                v = *reinterpret_cast<const float4*>(g_t + (size_t)tok * Hn + k0 + kq);
            As[kq + 0][m] = v.x; As[kq + 1][m] = v.y;
            As[kq + 2][m] = v.z; As[kq + 3][m] = v.w;
        }
        {
            int kk = tid >> 4;
            int n4 = (tid & 15) << 2;
            float4 v = *reinterpret_cast<const float4*>(W1 + (size_t)(k0 + kk) * Hn + n0 + n4);
            *reinterpret_cast<float4*>(&Bs[kk][n4]) = v;
        }
        __syncthreads();
#pragma unroll
        for (int k = 0; k < BKt; k++) {
            float4 a0 = *reinterpret_cast<const float4*>(&As[k][ty * TM]);
            float4 a1 = *reinterpret_cast<const float4*>(&As[k][ty * TM + 4]);
            float4 bv = *reinterpret_cast<const float4*>(&Bs[k][tx * TN]);
            float aa[TM] = {a0.x, a0.y, a0.z, a0.w, a1.x, a1.y, a1.z, a1.w};
            float bb[TN] = {bv.x, bv.y, bv.z, bv.w};
#pragma unroll
            for (int i = 0; i < TM; i++)
#pragma unroll
                for (int j = 0; j < TN; j++)
                    acc[i][j] = fmaf(aa[i], bb[j], acc[i][j]);
        }
        __syncthreads();
    }
#pragma unroll
    for (int i = 0; i < TM; i++) {
        int midx = ty * TM + i;
        int tok = toks[midx];
        if (tok < 0) continue;
        float4 o;
        o.x = fmaxf(acc[i][0], 0.f);
        o.y = fmaxf(acc[i][1], 0.f);
        o.z = fmaxf(acc[i][2], 0.f);
        o.w = fmaxf(acc[i][3], 0.f);
        *reinterpret_cast<float4*>(g_y + (size_t)slots[midx] * (Bn * Hn)
                                   + (size_t)tok * Hn + n0 + tx * TN) = o;
    }
}

// ---------------- combine: t += g1*y0 + g2*y1 ----------------
__global__ void combine_k() {
    size_t i = (size_t)blockIdx.x * 256 + threadIdx.x;  // float4 index over Bn*Hn/4
    int b = (int)(i >> 8);                              // Hn/4 = 256 float4 per row
    float G1 = g_g1[b], G2 = g_g2[b];
    float4 t  = reinterpret_cast<float4*>(g_t)[i];
    float4 y0 = reinterpret_cast<const float4*>(g_y)[i];
    float4 y1 = reinterpret_cast<const float4*>(g_y)[(size_t)(Bn * Hn / 4) + i];
    t.x += G1 * y0.x + G2 * y1.x;
    t.y += G1 * y0.y + G2 * y1.y;
    t.z += G1 * y0.z + G2 * y1.z;
    t.w += G1 * y0.w + G2 * y1.w;
    reinterpret_cast<float4*>(g_t)[i] = t;
}

// ---------------- batchnorm stats (double partial sums, deterministic) ----------------
__global__ void bn_partial_k() {
    __shared__ double ss[8][33];
    int tx = threadIdx.x & 31, ty = threadIdx.x >> 5;
    int col = blockIdx.x * 32 + tx;
    int r0 = blockIdx.y * 256;
    double s = 0.0, q = 0.0;
#pragma unroll 4
    for (int j = 0; j < 32; j++) {
        float v = g_t[(size_t)(r0 + ty + j * 8) * Hn + col];
        s += (double)v;
        q += (double)v * (double)v;
    }
    ss[ty][tx] = s; __syncthreads();
    if (ty == 0) {
        for (int j = 1; j < 8; j++) s += ss[j][tx];
        g_psum[blockIdx.y * Hn + col] = s;
    }
    __syncthreads();
    ss[ty][tx] = q; __syncthreads();
    if (ty == 0) {
        for (int j = 1; j < 8; j++) q += ss[j][tx];
        g_psq[blockIdx.y * Hn + col] = q;
    }
}

__global__ void bn_final_k(const float* __restrict__ gamma, const float* __restrict__ beta) {
    int col = blockIdx.x * 256 + threadIdx.x;
    double s = 0.0, q = 0.0;
    for (int j = 0; j < 8; j++) { s += g_psum[j * Hn + col]; q += g_psq[j * Hn + col]; }
    double mu = s / (double)Bn;
    float var = (float)(q / (double)Bn - mu * mu);
    float r = rsqrtf(var + 1e-5f);
    float a = gamma[col] * r;
    g_scale[col] = a;
    g_shift[col] = beta[col] - (float)mu * a;
}

__global__ void bn_apply_k() {
    size_t i = (size_t)blockIdx.x * 256 + threadIdx.x;  // float4 index
    int col = (int)((i & (Hn / 4 - 1)) << 2);
    float4 v = reinterpret_cast<const float4*>(g_t)[i];
    v.x = fmaxf(fmaf(v.x, g_scale[col + 0], g_shift[col + 0]), 0.f);
    v.y = fmaxf(fmaf(v.y, g_scale[col + 1], g_shift[col + 1]), 0.f);
    v.z = fmaxf(fmaf(v.z, g_scale[col + 2], g_shift[col + 2]), 0.f);
    v.w = fmaxf(fmaf(v.w, g_scale[col + 3], g_shift[col + 3]), 0.f);
    reinterpret_cast<float4*>(g_h)[i] = v;
}

// ---------------- loss write ----------------
__global__ void loss_k(float* __restrict__ out, int out_size) {
    if (out_size > Bn * OUTN)
        out[Bn * OUTN] = 0.01f * ((float)En / (float)Bn) * g_loss[0];
}

// ---------------- launcher ----------------
extern "C" void kernel_launch(void* const* d_in, const int* in_sizes, int n_in,
                              void* d_out, int out_size) {
    const float* x      = (const float*)d_in[0];
    const float* in_W   = (const float*)d_in[1];
    const float* in_b   = (const float*)d_in[2];
    const float* in_g   = (const float*)d_in[3];
    const float* in_be  = (const float*)d_in[4];
    const float* sp_W   = (const float*)d_in[5];
    const float* sp_b   = (const float*)d_in[6];
    const float* sp_g   = (const float*)d_in[7];
    const float* sp_be  = (const float*)d_in[8];
    const float* sp_gate= (const float*)d_in[9];
    const float* sp_w1  = (const float*)d_in[10];
    const float* dn_W   = (const float*)d_in[11];
    const float* dn_b   = (const float*)d_in[12];
    const float* dn_g   = (const float*)d_in[13];
    const float* dn_be  = (const float*)d_in[14];
    const float* out_W  = (const float*)d_in[15];
    const float* out_b  = (const float*)d_in[16];
    float* out = (float*)d_out;

    float* pt = nullptr; float* ph = nullptr;
    cudaGetSymbolAddress((void**)&pt, g_t);
    cudaGetSymbolAddress((void**)&ph, g_h);

    dim3 gemmGrid(Hn / BNt, Bn / BM);
    dim3 bnPartGrid(Hn / 32, 8);
    const int ew = Bn * Hn / 4 / 256;   // 2048 blocks for elementwise kernels

    init_k<<<1, 1>>>();

    // input layer: relu(bn(x @ in_W + in_b))
    gemm_bias<<<gemmGrid, 256>>>(x, in_W, in_b, pt, 2048, Hn);
    bn_partial_k<<<bnPartGrid, 256>>>();
    bn_final_k<<<Hn / 256, 256>>>(in_g, in_be);
    bn_apply_k<<<ew, 256>>>();

    // 4 sparse (MoE) layers
    for (int i = 0; i < 4; i++) {
        gemm_bias<<<gemmGrid, 256>>>(ph, sp_W + (size_t)i * Hn * Hn,
                                     sp_b + (size_t)i * Hn, pt, Hn, Hn);
        reset_cnt_k<<<1, 32>>>();
        gating_k<<<Bn / 8, 256>>>(sp_gate + (size_t)i * Hn * En, i);
        dim3 eg(Hn / BNt, Bn / BM, En);
        expert_gemm<<<eg, 256>>>(sp_w1, i);
        combine_k<<<ew, 256>>>();
        bn_partial_k<<<bnPartGrid, 256>>>();
        bn_final_k<<<Hn / 256, 256>>>(sp_g + (size_t)i * Hn, sp_be + (size_t)i * Hn);
        bn_apply_k<<<ew, 256>>>();
    }

    // 4 dense layers
    for (int i = 0; i < 4; i++) {
        gemm_bias<<<gemmGrid, 256>>>(ph, dn_W + (size_t)i * Hn * Hn,
                                     dn_b + (size_t)i * Hn, pt, Hn, Hn);
        bn_partial_k<<<bnPartGrid, 256>>>();
        bn_final_k<<<Hn / 256, 256>>>(dn_g + (size_t)i * Hn, dn_be + (size_t)i * Hn);
        bn_apply_k<<<ew, 256>>>();
    }

    // output projection + loss
    dim3 outGrid(OUTN / BNt, Bn / BM);
    gemm_bias<<<outGrid, 256>>>(ph, out_W, out_b, out, Hn, OUTN);
    loss_k<<<1, 1>>>(out, out_size);
}